// round 2
// baseline (speedup 1.0000x reference)
#include <cuda_runtime.h>

// Problem constants (fixed by the dataset)
#define B_   16
#define N_   1024
#define M_   12
#define FB_  32
#define F_   128
#define ROWS_TOT (B_ * N_)   // 16384

// Scratch (allocation-free rule: device globals)
__device__ float g_p[ROWS_TOT];
__device__ float g_colsum[N_];
__device__ float g_s[ROWS_TOT];

// ---------------------------------------------------------------------------
// Kernel 1: per-(b,n) bond statistic  p = prod(r) / max(sum(r),eps)^12,
//           r_m = 1 / ||bond[b,n,m,:]||^2.  One warp per row.
// ---------------------------------------------------------------------------
__global__ void bond_kernel(const float* __restrict__ bond) {
    int row  = (blockIdx.x << 3) + (threadIdx.x >> 5);   // 8 warps/block
    int lane = threadIdx.x & 31;
    const float* base = bond + (size_t)row * (M_ * FB_);
    float sumr = 0.f, prodr = 1.f;
#pragma unroll
    for (int m = 0; m < M_; ++m) {
        float v  = base[(m << 5) + lane];
        float sq = v * v;
#pragma unroll
        for (int off = 16; off; off >>= 1)
            sq += __shfl_xor_sync(0xffffffffu, sq, off);
        float nrm = sqrtf(sq);          // match reference: sqrt then ^-2
        float r   = 1.0f / (nrm * nrm);
        sumr  += r;
        prodr *= r;
    }
    if (lane == 0) {
        float D  = fmaxf(sumr, 1e-12f);
        float d2 = D * D, d4 = d2 * d2, d8 = d4 * d4;
        g_p[row] = prodr / (d8 * d4);   // / D^12
    }
}

// ---------------------------------------------------------------------------
// Kernel 2: colsum[n] = sum_b p[b,n]
// ---------------------------------------------------------------------------
__global__ void colsum_kernel() {
    int n = blockIdx.x * blockDim.x + threadIdx.x;
    float s = 0.f;
#pragma unroll
    for (int b = 0; b < B_; ++b) s += g_p[b * N_ + n];
    g_colsum[n] = s;
}

// ---------------------------------------------------------------------------
// Kernel 3: u = max(colsum,eps)/p ; s[b,n] = u / max(sum_n u, eps)
//           One block per batch b.
// ---------------------------------------------------------------------------
__global__ void s_kernel() {
    __shared__ float red[256];
    int b = blockIdx.x, tid = threadIdx.x;
    float u[4];
    float loc = 0.f;
#pragma unroll
    for (int j = 0; j < 4; ++j) {
        int n    = tid + (j << 8);
        float cs = fmaxf(g_colsum[n], 1e-12f);
        u[j]     = cs / g_p[b * N_ + n];
        loc     += u[j];
    }
    red[tid] = loc;
    __syncthreads();
    for (int off = 128; off; off >>= 1) {
        if (tid < off) red[tid] += red[tid + off];
        __syncthreads();
    }
    float inv = 1.0f / fmaxf(red[0], 1e-12f);
#pragma unroll
    for (int j = 0; j < 4; ++j)
        g_s[b * N_ + (tid + (j << 8))] = u[j] * inv;
}

// ---------------------------------------------------------------------------
// Kernel 4: fused gather + mean + scale + GEMM(16384x128x128) + bias + ReLU
//   Block: 256 threads, 32 output rows, all 128 output cols.
//   A-tile built in smem from gathered atom rows; W staged in K-chunks of 32.
//   Thread microtile: 4 rows x 4 cols.
// ---------------------------------------------------------------------------
__global__ __launch_bounds__(256) void fused_kernel(
    const float* __restrict__ atom, const int* __restrict__ adj,
    const float* __restrict__ W, const float* __restrict__ bias,
    float* __restrict__ out)
{
    __shared__ float sA[32][F_];        // 16 KB
    __shared__ float sW[32 * F_];       // 16 KB (K-chunk of W)

    int tid  = threadIdx.x;
    int wid  = tid >> 5;                // 0..7
    int lane = tid & 31;
    int row0 = blockIdx.x << 5;

    // ---- Build A tile: each warp produces 4 rows, lane owns 4 columns ----
#pragma unroll
    for (int rr = 0; rr < 4; ++rr) {
        int r = (wid << 2) + rr;
        int g = row0 + r;                        // global row = b*N + n
        int b = g >> 10;
        const float* arow  = atom + ((size_t)g << 7);
        const float* abase = atom + ((size_t)b << 17);   // b*N*F
        int myidx = (lane < M_) ? adj[(size_t)g * M_ + lane] : 0;

        float4 self = *(const float4*)(arow + (lane << 2));
        float ax = 0.f, ay = 0.f, az = 0.f, aw = 0.f;
#pragma unroll
        for (int m = 0; m < M_; ++m) {
            int idx = __shfl_sync(0xffffffffu, myidx, m) & (N_ - 1);
            float4 nb = *(const float4*)(abase + ((size_t)idx << 7) + (lane << 2));
            ax += nb.x; ay += nb.y; az += nb.z; aw += nb.w;
        }
        float sc = g_s[g];
        const float inv12 = 1.0f / 12.0f;
        float4 av;
        av.x = (self.x + ax * inv12) * sc;
        av.y = (self.y + ay * inv12) * sc;
        av.z = (self.z + az * inv12) * sc;
        av.w = (self.w + aw * inv12) * sc;
        *(float4*)&sA[r][lane << 2] = av;
    }
    __syncthreads();

    // ---- GEMM: acc[4][4], K in 4 chunks of 32 ----
    int ty = wid, tx = lane;
    float acc[4][4];
#pragma unroll
    for (int j = 0; j < 4; ++j)
#pragma unroll
        for (int i = 0; i < 4; ++i) acc[j][i] = 0.f;

#pragma unroll
    for (int kc = 0; kc < 4; ++kc) {
        // stage W rows [kc*32, kc*32+32)
#pragma unroll
        for (int t = 0; t < 4; ++t) {
            int q = tid + (t << 8);   // float4 index within 32x128 chunk
            ((float4*)sW)[q] = ((const float4*)(W + (size_t)(kc << 5) * F_))[q];
        }
        __syncthreads();
#pragma unroll
        for (int kk = 0; kk < 32; ++kk) {
            float4 wv = *(const float4*)&sW[kk * F_ + (tx << 2)];
#pragma unroll
            for (int j = 0; j < 4; ++j) {
                float a = sA[(ty << 2) + j][(kc << 5) + kk];  // warp-broadcast
                acc[j][0] += a * wv.x;
                acc[j][1] += a * wv.y;
                acc[j][2] += a * wv.z;
                acc[j][3] += a * wv.w;
            }
        }
        __syncthreads();
    }

    // ---- Epilogue: bias + ReLU ----
    float4 bv = *(const float4*)(bias + (tx << 2));
#pragma unroll
    for (int j = 0; j < 4; ++j) {
        int g = row0 + (ty << 2) + j;
        float4 o;
        o.x = fmaxf(acc[j][0] + bv.x, 0.f);
        o.y = fmaxf(acc[j][1] + bv.y, 0.f);
        o.z = fmaxf(acc[j][2] + bv.z, 0.f);
        o.w = fmaxf(acc[j][3] + bv.w, 0.f);
        *(float4*)(out + ((size_t)g << 7) + (tx << 2)) = o;
    }
}

// ---------------------------------------------------------------------------
extern "C" void kernel_launch(void* const* d_in, const int* in_sizes, int n_in,
                              void* d_out, int out_size) {
    const float* atom = (const float*)d_in[0];
    const float* bond = (const float*)d_in[1];
    const int*   adj  = (const int*)d_in[2];
    const float* W    = (const float*)d_in[3];
    const float* bias = (const float*)d_in[4];
    float*       out  = (float*)d_out;

    bond_kernel  <<<ROWS_TOT / 8, 256>>>(bond);
    colsum_kernel<<<N_ / 256, 256>>>();
    s_kernel     <<<B_, 256>>>();
    fused_kernel <<<ROWS_TOT / 32, 256>>>(atom, adj, W, bias, out);
}

// round 3
// speedup vs baseline: 1.2123x; 1.2123x over previous
#include <cuda_runtime.h>

#define B_   16
#define N_   1024
#define M_   12
#define FB_  32
#define F_   128
#define ROWS_TOT (B_ * N_)   // 16384

__device__ float g_p[ROWS_TOT];
__device__ float g_s[ROWS_TOT];

// ---------------------------------------------------------------------------
// Kernel 1: p[b,n] = prod_m r_m / max(sum_m r_m,eps)^12,  r_m = 1/||bond||^2
// One warp per row; 8 lanes per m-vector (FB=32 -> float4 per lane).
// ---------------------------------------------------------------------------
__global__ void bond_kernel(const float* __restrict__ bond) {
    int row  = (blockIdx.x << 3) + (threadIdx.x >> 5);
    int lane = threadIdx.x & 31;
    int grp  = lane >> 3;          // 0..3 : which m within quartet
    int sub  = lane & 7;           // 0..7 : float4 slot within FB=32
    const float* base = bond + (size_t)row * (M_ * FB_);

    float sumr = 0.f, prodr = 1.f;
#pragma unroll
    for (int i = 0; i < 3; ++i) {
        int m = (i << 2) + grp;
        float4 v = *(const float4*)(base + (m << 5) + (sub << 2));
        float sq = v.x*v.x + v.y*v.y + v.z*v.z + v.w*v.w;
        sq += __shfl_xor_sync(0xffffffffu, sq, 1);
        sq += __shfl_xor_sync(0xffffffffu, sq, 2);
        sq += __shfl_xor_sync(0xffffffffu, sq, 4);
        float nrm = sqrtf(sq);            // match reference: sqrt then ^-2
        float r   = 1.0f / (nrm * nrm);
        sumr  += r;
        prodr *= r;
    }
    // combine the 4 m-groups (lanes within a group hold identical values)
    sumr  += __shfl_xor_sync(0xffffffffu, sumr, 8);
    sumr  += __shfl_xor_sync(0xffffffffu, sumr, 16);
    prodr *= __shfl_xor_sync(0xffffffffu, prodr, 8);
    prodr *= __shfl_xor_sync(0xffffffffu, prodr, 16);

    if (lane == 0) {
        float D  = fmaxf(sumr, 1e-12f);
        float d2 = D * D, d4 = d2 * d2, d8 = d4 * d4;
        g_p[row] = prodr / (d8 * d4);     // / D^12
    }
}

// ---------------------------------------------------------------------------
// Kernel 2 (merged): colsum over B, u = max(colsum,eps)/p, s = u / sum_n u
// 16 blocks (one per b) x 1024 threads (one per n). g_p is L2-resident.
// ---------------------------------------------------------------------------
__global__ void s_kernel() {
    __shared__ float red[32];
    int b = blockIdx.x, n = threadIdx.x;
    int wid = n >> 5, lane = n & 31;

    float cs = 0.f;
#pragma unroll
    for (int bb = 0; bb < B_; ++bb) cs += g_p[bb * N_ + n];
    float u = fmaxf(cs, 1e-12f) / g_p[b * N_ + n];

    float v = u;
#pragma unroll
    for (int off = 16; off; off >>= 1) v += __shfl_xor_sync(0xffffffffu, v, off);
    if (lane == 0) red[wid] = v;
    __syncthreads();
    if (wid == 0) {
        float t = red[lane];
#pragma unroll
        for (int off = 16; off; off >>= 1) t += __shfl_xor_sync(0xffffffffu, t, off);
        if (lane == 0) red[0] = 1.0f / fmaxf(t, 1e-12f);
    }
    __syncthreads();
    g_s[b * N_ + n] = u * red[0];
}

// ---------------------------------------------------------------------------
// Kernel 3: fused gather + mean + scale + GEMM + bias + ReLU
//   32 rows x 128 cols per block, 256 threads, 4x4 microtile.
//   A loaded as float4 over k; W double-buffered in 32-row chunks.
// ---------------------------------------------------------------------------
__global__ __launch_bounds__(256) void fused_kernel(
    const float* __restrict__ atom, const int* __restrict__ adj,
    const float* __restrict__ W, const float* __restrict__ bias,
    float* __restrict__ out)
{
    __shared__ float sA[32][F_];          // 16 KB
    __shared__ float sW[2][32 * F_];      // 32 KB (double-buffered K-chunks)

    int tid  = threadIdx.x;
    int wid  = tid >> 5;
    int lane = tid & 31;
    int row0 = blockIdx.x << 5;

    // ---- stage W chunk 0 into buffer 0 ----
    {
        const float4* src = (const float4*)W;
        float4* dst = (float4*)sW[0];
#pragma unroll
        for (int t = 0; t < 4; ++t) dst[tid + (t << 8)] = src[tid + (t << 8)];
    }

    // ---- Build A tile: each warp produces 4 rows, lane owns 4 columns ----
#pragma unroll
    for (int rr = 0; rr < 4; ++rr) {
        int r = (wid << 2) + rr;
        int g = row0 + r;
        int b = g >> 10;
        const float* arow  = atom + ((size_t)g << 7);
        const float* abase = atom + ((size_t)b << 17);
        int myidx = (lane < M_) ? adj[(size_t)g * M_ + lane] : 0;

        float4 self = *(const float4*)(arow + (lane << 2));
        float ax = 0.f, ay = 0.f, az = 0.f, aw = 0.f;
#pragma unroll
        for (int m = 0; m < M_; ++m) {
            int idx = __shfl_sync(0xffffffffu, myidx, m) & (N_ - 1);
            float4 nb = *(const float4*)(abase + ((size_t)idx << 7) + (lane << 2));
            ax += nb.x; ay += nb.y; az += nb.z; aw += nb.w;
        }
        float sc = g_s[g];
        const float inv12 = 1.0f / 12.0f;
        float4 av;
        av.x = (self.x + ax * inv12) * sc;
        av.y = (self.y + ay * inv12) * sc;
        av.z = (self.z + az * inv12) * sc;
        av.w = (self.w + aw * inv12) * sc;
        *(float4*)&sA[r][lane << 2] = av;
    }
    __syncthreads();

    // ---- GEMM: 4 chunks of 32 k, double-buffered W ----
    float acc[4][4];
#pragma unroll
    for (int j = 0; j < 4; ++j)
#pragma unroll
        for (int i = 0; i < 4; ++i) acc[j][i] = 0.f;

#pragma unroll
    for (int kc = 0; kc < 4; ++kc) {
        if (kc < 3) {   // prefetch next chunk into the other buffer
            const float4* src = (const float4*)(W + (size_t)((kc + 1) << 5) * F_);
            float4* dst = (float4*)sW[(kc + 1) & 1];
#pragma unroll
            for (int t = 0; t < 4; ++t) dst[tid + (t << 8)] = src[tid + (t << 8)];
        }
        const float* wb = sW[kc & 1];
        int kb = kc << 5;
#pragma unroll
        for (int k4 = 0; k4 < 8; ++k4) {
            float a0[4], a1[4], a2[4], a3[4];
            *(float4*)a0 = *(const float4*)&sA[(wid << 2) + 0][kb + (k4 << 2)];
            *(float4*)a1 = *(const float4*)&sA[(wid << 2) + 1][kb + (k4 << 2)];
            *(float4*)a2 = *(const float4*)&sA[(wid << 2) + 2][kb + (k4 << 2)];
            *(float4*)a3 = *(const float4*)&sA[(wid << 2) + 3][kb + (k4 << 2)];
#pragma unroll
            for (int q = 0; q < 4; ++q) {
                float4 wv = *(const float4*)&wb[((k4 << 2) + q) * F_ + (lane << 2)];
                acc[0][0] += a0[q] * wv.x; acc[0][1] += a0[q] * wv.y;
                acc[0][2] += a0[q] * wv.z; acc[0][3] += a0[q] * wv.w;
                acc[1][0] += a1[q] * wv.x; acc[1][1] += a1[q] * wv.y;
                acc[1][2] += a1[q] * wv.z; acc[1][3] += a1[q] * wv.w;
                acc[2][0] += a2[q] * wv.x; acc[2][1] += a2[q] * wv.y;
                acc[2][2] += a2[q] * wv.z; acc[2][3] += a2[q] * wv.w;
                acc[3][0] += a3[q] * wv.x; acc[3][1] += a3[q] * wv.y;
                acc[3][2] += a3[q] * wv.z; acc[3][3] += a3[q] * wv.w;
            }
        }
        __syncthreads();
    }

    // ---- Epilogue: bias + ReLU ----
    float4 bv = *(const float4*)(bias + (lane << 2));
#pragma unroll
    for (int j = 0; j < 4; ++j) {
        int g = row0 + (wid << 2) + j;
        float4 o;
        o.x = fmaxf(acc[j][0] + bv.x, 0.f);
        o.y = fmaxf(acc[j][1] + bv.y, 0.f);
        o.z = fmaxf(acc[j][2] + bv.z, 0.f);
        o.w = fmaxf(acc[j][3] + bv.w, 0.f);
        *(float4*)(out + ((size_t)g << 7) + (lane << 2)) = o;
    }
}

// ---------------------------------------------------------------------------
extern "C" void kernel_launch(void* const* d_in, const int* in_sizes, int n_in,
                              void* d_out, int out_size) {
    const float* atom = (const float*)d_in[0];
    const float* bond = (const float*)d_in[1];
    const int*   adj  = (const int*)d_in[2];
    const float* W    = (const float*)d_in[3];
    const float* bias = (const float*)d_in[4];
    float*       out  = (float*)d_out;

    bond_kernel <<<ROWS_TOT / 8, 256>>>(bond);
    s_kernel    <<<B_, 1024>>>();
    fused_kernel<<<ROWS_TOT / 32, 256>>>(atom, adj, W, bias, out);
}

// round 4
// speedup vs baseline: 1.4102x; 1.1632x over previous
#include <cuda_runtime.h>

#define B_   16
#define N_   1024
#define M_   12
#define FB_  32
#define F_   128
#define ROWS_TOT (B_ * N_)   // 16384

__device__ float g_p[ROWS_TOT];
__device__ float g_s[ROWS_TOT];

// ---------------------------------------------------------------------------
// Kernel 1: p[b,n] = prod_m r_m / max(sum_m r_m,eps)^12,  r_m = 1/||bond||^2
// One warp per TWO rows (6 independent LDG.128 per thread for MLP).
// 8 lanes per m-vector; grp = lane>>3 selects m within quartet.
// ---------------------------------------------------------------------------
__global__ void bond_kernel(const float* __restrict__ bond) {
    int warp = (blockIdx.x << 3) + (threadIdx.x >> 5);
    int lane = threadIdx.x & 31;
    int grp  = lane >> 3;
    int sub  = lane & 7;
    int row0 = warp << 1;
    const float* b0 = bond + (size_t)row0 * (M_ * FB_);
    const float* b1 = b0 + (M_ * FB_);

    // issue all 6 loads up front
    float4 v0[3], v1[3];
#pragma unroll
    for (int i = 0; i < 3; ++i) {
        int off = (((i << 2) + grp) << 5) + (sub << 2);
        v0[i] = *(const float4*)(b0 + off);
        v1[i] = *(const float4*)(b1 + off);
    }

    float sum0 = 0.f, prod0 = 1.f, sum1 = 0.f, prod1 = 1.f;
#pragma unroll
    for (int i = 0; i < 3; ++i) {
        float s0 = v0[i].x*v0[i].x + v0[i].y*v0[i].y + v0[i].z*v0[i].z + v0[i].w*v0[i].w;
        float s1 = v1[i].x*v1[i].x + v1[i].y*v1[i].y + v1[i].z*v1[i].z + v1[i].w*v1[i].w;
#pragma unroll
        for (int off = 1; off <= 4; off <<= 1) {
            s0 += __shfl_xor_sync(0xffffffffu, s0, off);
            s1 += __shfl_xor_sync(0xffffffffu, s1, off);
        }
        float r0 = 1.0f / s0;          // (sqrt(s))^-2 == 1/s
        float r1 = 1.0f / s1;
        sum0 += r0; prod0 *= r0;
        sum1 += r1; prod1 *= r1;
    }
#pragma unroll
    for (int off = 8; off <= 16; off <<= 1) {
        sum0  += __shfl_xor_sync(0xffffffffu, sum0, off);
        sum1  += __shfl_xor_sync(0xffffffffu, sum1, off);
        prod0 *= __shfl_xor_sync(0xffffffffu, prod0, off);
        prod1 *= __shfl_xor_sync(0xffffffffu, prod1, off);
    }
    if (lane == 0) {
        float D  = fmaxf(sum0, 1e-12f);
        float d2 = D*D, d4 = d2*d2;
        g_p[row0] = prod0 / (d4*d4*d4);
    } else if (lane == 1) {
        float D  = fmaxf(sum1, 1e-12f);
        float d2 = D*D, d4 = d2*d2;
        g_p[row0 + 1] = prod1 / (d4*d4*d4);
    }
}

// ---------------------------------------------------------------------------
// Kernel 2: colsum over B, u = max(colsum,eps)/p, s = u / sum_n u
// 16 blocks (one per b) x 1024 threads (one per n). g_p is L2-resident.
// ---------------------------------------------------------------------------
__global__ void s_kernel() {
    __shared__ float red[32];
    int b = blockIdx.x, n = threadIdx.x;
    int wid = n >> 5, lane = n & 31;

    float cs = 0.f;
#pragma unroll
    for (int bb = 0; bb < B_; ++bb) cs += g_p[bb * N_ + n];
    float u = fmaxf(cs, 1e-12f) / g_p[b * N_ + n];

    float v = u;
#pragma unroll
    for (int off = 16; off; off >>= 1) v += __shfl_xor_sync(0xffffffffu, v, off);
    if (lane == 0) red[wid] = v;
    __syncthreads();
    if (wid == 0) {
        float t = red[lane];
#pragma unroll
        for (int off = 16; off; off >>= 1) t += __shfl_xor_sync(0xffffffffu, t, off);
        if (lane == 0) red[0] = 1.0f / fmaxf(t, 1e-12f);
    }
    __syncthreads();
    g_s[b * N_ + n] = u * red[0];
}

// ---------------------------------------------------------------------------
// Kernel 3: fused gather + mean + scale + GEMM + bias + ReLU
//   Block: 256 threads, 64 rows x 128 cols. Thread microtile: 8 rows x 4 cols.
//   Inner product uses packed fma.rn.f32x2 (2 MACs/instr on the fma pipe).
// ---------------------------------------------------------------------------
__global__ __launch_bounds__(256) void fused_kernel(
    const float* __restrict__ atom, const int* __restrict__ adj,
    const float* __restrict__ W, const float* __restrict__ bias,
    float* __restrict__ out)
{
    __shared__ float sA[64][F_];       // 32 KB
    __shared__ float sW[32][F_];       // 16 KB (K-chunk)

    int tid  = threadIdx.x;
    int wid  = tid >> 5;
    int lane = tid & 31;
    int row0 = blockIdx.x << 6;        // 64 rows per block

    // ---- Build A tile: each warp produces 8 rows ----
#pragma unroll
    for (int rr = 0; rr < 8; ++rr) {
        int r = (wid << 3) + rr;
        int g = row0 + r;
        int b = g >> 10;
        const float* arow  = atom + ((size_t)g << 7);
        const float* abase = atom + ((size_t)b << 17);
        int myidx = (lane < M_) ? adj[(size_t)g * M_ + lane] : 0;

        float4 self = *(const float4*)(arow + (lane << 2));
        float ax = 0.f, ay = 0.f, az = 0.f, aw = 0.f;
#pragma unroll
        for (int m = 0; m < M_; ++m) {
            int idx = __shfl_sync(0xffffffffu, myidx, m) & (N_ - 1);
            float4 nb = *(const float4*)(abase + ((size_t)idx << 7) + (lane << 2));
            ax += nb.x; ay += nb.y; az += nb.z; aw += nb.w;
        }
        float sc = g_s[g];
        const float inv12 = 1.0f / 12.0f;
        float4 av;
        av.x = (self.x + ax * inv12) * sc;
        av.y = (self.y + ay * inv12) * sc;
        av.z = (self.z + az * inv12) * sc;
        av.w = (self.w + aw * inv12) * sc;
        *(float4*)&sA[r][lane << 2] = av;
    }

    // ---- GEMM with packed f32x2 accumulators ----
    unsigned long long acc[8][2];
#pragma unroll
    for (int r = 0; r < 8; ++r) { acc[r][0] = 0ull; acc[r][1] = 0ull; }

#pragma unroll
    for (int kc = 0; kc < 4; ++kc) {
        __syncthreads();               // also covers A-build on kc==0
        {
            const float4* src = (const float4*)(W + (size_t)(kc << 5) * F_);
            float4* dst = (float4*)sW;
#pragma unroll
            for (int t = 0; t < 4; ++t) dst[tid + (t << 8)] = src[tid + (t << 8)];
        }
        __syncthreads();

        int kb = kc << 5;
#pragma unroll
        for (int kk = 0; kk < 32; ++kk) {
            // W row k, this lane's 4 columns, as two packed f32x2
            const unsigned long long* wp =
                (const unsigned long long*)&sW[kk][lane << 2];
            unsigned long long w01 = wp[0], w23 = wp[1];
#pragma unroll
            for (int r = 0; r < 8; ++r) {
                float a = sA[(wid << 3) + r][kb + kk];   // warp-broadcast LDS
                unsigned long long a2;
                asm("mov.b64 %0, {%1, %1};" : "=l"(a2) : "f"(a));
                asm("fma.rn.f32x2 %0, %1, %2, %0;" : "+l"(acc[r][0]) : "l"(a2), "l"(w01));
                asm("fma.rn.f32x2 %0, %1, %2, %0;" : "+l"(acc[r][1]) : "l"(a2), "l"(w23));
            }
        }
    }

    // ---- Epilogue: unpack + bias + ReLU ----
    float4 bv = *(const float4*)(bias + (lane << 2));
#pragma unroll
    for (int r = 0; r < 8; ++r) {
        int g = row0 + (wid << 3) + r;
        float c0, c1, c2, c3;
        asm("mov.b64 {%0, %1}, %2;" : "=f"(c0), "=f"(c1) : "l"(acc[r][0]));
        asm("mov.b64 {%0, %1}, %2;" : "=f"(c2), "=f"(c3) : "l"(acc[r][1]));
        float4 o;
        o.x = fmaxf(c0 + bv.x, 0.f);
        o.y = fmaxf(c1 + bv.y, 0.f);
        o.z = fmaxf(c2 + bv.z, 0.f);
        o.w = fmaxf(c3 + bv.w, 0.f);
        *(float4*)(out + ((size_t)g << 7) + (lane << 2)) = o;
    }
}

// ---------------------------------------------------------------------------
extern "C" void kernel_launch(void* const* d_in, const int* in_sizes, int n_in,
                              void* d_out, int out_size) {
    const float* atom = (const float*)d_in[0];
    const float* bond = (const float*)d_in[1];
    const int*   adj  = (const int*)d_in[2];
    const float* W    = (const float*)d_in[3];
    const float* bias = (const float*)d_in[4];
    float*       out  = (float*)d_out;

    bond_kernel <<<ROWS_TOT / 16, 256>>>(bond);
    s_kernel    <<<B_, 1024>>>();
    fused_kernel<<<ROWS_TOT / 64, 256>>>(atom, adj, W, bias, out);
}